// round 16
// baseline (speedup 1.0000x reference)
#include <cuda_runtime.h>

// NoQmix q_tot reduction.
//
// Reference: attention = softmax(e, axis=1) => sum_i att[b,i,j] = 1 for every
// (b,j) (fully-masked columns degenerate to uniform 1/64, still summing to 1),
// so q_tot[b] = sum_j agent_qs[b,j]. Verified on hardware R14:
// rel_err = 1.69e-7 (softmax normalization noise only).
//
// R14 profile: 4.29us kernel, all pipes <7% => launch-overhead + MLP=1 DRAM
// latency bound. This revision: 4x fewer warps (512), each with 4 independent
// front-batched LDG.128 (MLP=4) covering 8 rows, to amortize the 577-cycle
// DRAM latency and shrink dispatch work.
//
// Inputs (metadata order): 0 features, 1 agent_qs (4096*64 f32), 2 adj,
// 3 states, 4 W, 5 a. Output: 4096 f32 (shape (4096,1,1)).

#define NQ_B 4096
#define NQ_N 64

// Each warp handles 8 rows as 4 independent "2-row" groups.
// Group k: lanes 0-15 -> row 8w+2k, lanes 16-31 -> row 8w+2k+1.
// Each lane loads one float4 per group; 32 lanes * 16B = 512B = 2 rows.
__global__ void noqmix_sum_qs_kernel(const float4* __restrict__ qs4,
                                     float* __restrict__ out) {
    const int gwarp = (blockIdx.x * blockDim.x + threadIdx.x) >> 5;  // warp id
    const int lane  = threadIdx.x & 31;
    const int base_pair = gwarp * 4;          // first of 4 row-pairs
    if (base_pair >= NQ_B / 2) return;

    // Front-batched independent loads (MLP=4). Each is 512B coalesced.
    float4 v0 = qs4[(size_t)(base_pair + 0) * 32 + lane];
    float4 v1 = qs4[(size_t)(base_pair + 1) * 32 + lane];
    float4 v2 = qs4[(size_t)(base_pair + 2) * 32 + lane];
    float4 v3 = qs4[(size_t)(base_pair + 3) * 32 + lane];

    float s0 = (v0.x + v0.y) + (v0.z + v0.w);
    float s1 = (v1.x + v1.y) + (v1.z + v1.w);
    float s2 = (v2.x + v2.y) + (v2.z + v2.w);
    float s3 = (v3.x + v3.y) + (v3.z + v3.w);

    // Independent butterfly chains — pipeline through the SHFL unit.
    #pragma unroll
    for (int off = 8; off > 0; off >>= 1) {
        s0 += __shfl_xor_sync(0xFFFFFFFFu, s0, off);
        s1 += __shfl_xor_sync(0xFFFFFFFFu, s1, off);
        s2 += __shfl_xor_sync(0xFFFFFFFFu, s2, off);
        s3 += __shfl_xor_sync(0xFFFFFFFFu, s3, off);
    }

    // lanes 0 and 16 hold the two row sums of each group.
    const int row0 = base_pair * 2;           // rows row0 .. row0+7
    if (lane == 0) {
        out[row0 + 0] = s0;
        out[row0 + 2] = s1;
        out[row0 + 4] = s2;
        out[row0 + 6] = s3;
    } else if (lane == 16) {
        out[row0 + 1] = s0;
        out[row0 + 3] = s1;
        out[row0 + 5] = s2;
        out[row0 + 7] = s3;
    }
}

extern "C" void kernel_launch(void* const* d_in, const int* in_sizes, int n_in,
                              void* d_out, int out_size) {
    const float4* agent_qs4 = (const float4*)d_in[1];
    float* out = (float*)d_out;

    // 512 warps -> 16384 threads -> 64 blocks of 256 (sub-wave, 64 SMs).
    const int threads = 256;
    const int blocks = (NQ_B / 8 * 32) / threads;  // 64
    noqmix_sum_qs_kernel<<<blocks, threads>>>(agent_qs4, out);
}